// round 2
// baseline (speedup 1.0000x reference)
#include <cuda_runtime.h>
#include <cuda_bf16.h>
#include <math.h>

// Problem constants
#define PB   4
#define PS   2048
#define PH   1024      // hidden = NH*HD
#define PNH  16
#define PHD  64
#define PWH  32        // window half = WIN//2
#define PM   (PB*PS)   // 8192 GEMM rows

// Scratch (allocation-free): q, k, v, attn-out, each [B,S,NH*HD] fp32
#define SCR_ELEMS (PB*PS*PH)
__device__ float g_q[SCR_ELEMS];
__device__ float g_k[SCR_ELEMS];
__device__ float g_v[SCR_ELEMS];
__device__ float g_a[SCR_ELEMS];

// ---------------------------------------------------------------------------
// GEMM: C[M,1024] = A[M,1024] @ W[1024,1024] + bias, fp32
// 128x128 block tile, 16 K-slab, 8x8 per thread, 256 threads
// ---------------------------------------------------------------------------
__global__ __launch_bounds__(256) void gemm_bias_kernel(
    const float* __restrict__ A, const float* __restrict__ W,
    const float* __restrict__ bias, float* __restrict__ C)
{
    constexpr int K = 1024, N = 1024;
    __shared__ float As[16][128];   // [k][m] (transposed on store)
    __shared__ float Bs[16][128];   // [k][n]

    const int tid = threadIdx.x;
    const int m0 = blockIdx.y * 128;
    const int n0 = blockIdx.x * 128;
    const int tr = tid >> 4;   // 0..15
    const int tc = tid & 15;   // 0..15

    float acc[8][8];
    #pragma unroll
    for (int i = 0; i < 8; i++)
        #pragma unroll
        for (int j = 0; j < 8; j++) acc[i][j] = 0.f;

    const float* Aptr = A + (size_t)m0 * K;
    const float* Wptr = W + n0;

    for (int k0 = 0; k0 < K; k0 += 16) {
        // Load A tile: 128 rows x 16 cols = 512 float4
        #pragma unroll
        for (int i = 0; i < 2; i++) {
            int idx = tid + i * 256;
            int r  = idx >> 2;
            int c4 = (idx & 3) << 2;
            float4 av = *(const float4*)(Aptr + (size_t)r * K + k0 + c4);
            As[c4 + 0][r] = av.x;
            As[c4 + 1][r] = av.y;
            As[c4 + 2][r] = av.z;
            As[c4 + 3][r] = av.w;
        }
        // Load W tile: 16 rows x 128 cols = 512 float4
        #pragma unroll
        for (int i = 0; i < 2; i++) {
            int idx = tid + i * 256;
            int r  = idx >> 5;
            int c4 = (idx & 31) << 2;
            *(float4*)(&Bs[r][c4]) = *(const float4*)(Wptr + (size_t)(k0 + r) * N + c4);
        }
        __syncthreads();

        #pragma unroll
        for (int kk = 0; kk < 16; kk++) {
            float a[8], b[8];
            *(float4*)(a)     = *(float4*)(&As[kk][tr * 8]);
            *(float4*)(a + 4) = *(float4*)(&As[kk][tr * 8 + 4]);
            *(float4*)(b)     = *(float4*)(&Bs[kk][tc * 8]);
            *(float4*)(b + 4) = *(float4*)(&Bs[kk][tc * 8 + 4]);
            #pragma unroll
            for (int i = 0; i < 8; i++)
                #pragma unroll
                for (int j = 0; j < 8; j++)
                    acc[i][j] += a[i] * b[j];
        }
        __syncthreads();
    }

    // Epilogue with bias, float4 stores
    float4 b0 = *(const float4*)(bias + n0 + tc * 8);
    float4 b1 = *(const float4*)(bias + n0 + tc * 8 + 4);
    #pragma unroll
    for (int i = 0; i < 8; i++) {
        int row = m0 + tr * 8 + i;
        float* Crow = C + (size_t)row * N + n0 + tc * 8;
        float4 o0, o1;
        o0.x = acc[i][0] + b0.x; o0.y = acc[i][1] + b0.y;
        o0.z = acc[i][2] + b0.z; o0.w = acc[i][3] + b0.w;
        o1.x = acc[i][4] + b1.x; o1.y = acc[i][5] + b1.y;
        o1.z = acc[i][6] + b1.z; o1.w = acc[i][7] + b1.w;
        *(float4*)(Crow)     = o0;
        *(float4*)(Crow + 4) = o1;
    }
}

// ---------------------------------------------------------------------------
// Banded attention: one block per (b, h, 32-query tile). 256 threads = 8 warps,
// warp per query (4 queries/warp). Lane l owns key-offsets l and l+32; offset
// 64 computed broadcast by all lanes. K tile + Q tile in static shared.
// ---------------------------------------------------------------------------
__global__ __launch_bounds__(256) void attn_kernel(
    const float* __restrict__ q, const float* __restrict__ k,
    const float* __restrict__ v, const int* __restrict__ mask,
    float* __restrict__ out)
{
    constexpr int QT = 32;            // queries per block
    constexpr int KT = QT + 2 * PWH;  // 96 keys in tile
    __shared__ float Ks[KT][PHD + 1]; // padded rows -> conflict-free banded reads
    __shared__ float Qs[QT][PHD];
    __shared__ float Pr[8][72];       // per-warp probabilities

    const int nqt = PS / QT;          // 64
    const int blk = blockIdx.x;
    const int qt = blk % nqt;
    const int h  = (blk / nqt) % PNH;
    const int b  = blk / (nqt * PNH);
    const int t0 = qt * QT;
    const int tid = threadIdx.x;
    const size_t base = ((size_t)b * PS) * PH + (size_t)h * PHD;

    // Load K tile (zero-fill out-of-range rows)
    for (int idx = tid; idx < KT * (PHD / 4); idx += 256) {
        int r  = idx >> 4;
        int c4 = (idx & 15) << 2;
        int jg = t0 - PWH + r;
        float4 kv = make_float4(0.f, 0.f, 0.f, 0.f);
        if (jg >= 0 && jg < PS)
            kv = *(const float4*)(k + base + (size_t)jg * PH + c4);
        Ks[r][c4 + 0] = kv.x; Ks[r][c4 + 1] = kv.y;
        Ks[r][c4 + 2] = kv.z; Ks[r][c4 + 3] = kv.w;
    }
    // Load Q tile
    for (int idx = tid; idx < QT * (PHD / 4); idx += 256) {
        int r  = idx >> 4;
        int c4 = (idx & 15) << 2;
        *(float4*)(&Qs[r][c4]) =
            *(const float4*)(q + base + (size_t)(t0 + r) * PH + c4);
    }
    __syncthreads();

    const int w = tid >> 5, l = tid & 31;
    const float inv_scale = 0.125f;  // 1/sqrt(64)

    for (int qi = w; qi < QT; qi += 8) {
        const int ig = t0 + qi;
        const int j0 = ig - PWH + l;
        const int j1 = j0 + 32;
        const int j2 = ig + PWH;
        const bool v0 = (j0 >= 0) && (j0 < PS) && (mask[b * PS + j0] != 0);
        const bool v1 = (j1 < PS) && (mask[b * PS + j1] != 0);
        const bool v2 = (j2 < PS) && (mask[b * PS + j2] != 0);

        float s0 = 0.f, s1 = 0.f, s2 = 0.f;
        #pragma unroll 16
        for (int d = 0; d < PHD; d++) {
            float qd = Qs[qi][d];
            s0 += qd * Ks[qi + l][d];
            s1 += qd * Ks[qi + l + 32][d];
            s2 += qd * Ks[qi + 64][d];
        }
        s0 = v0 ? s0 * inv_scale : -INFINITY;
        s1 = v1 ? s1 * inv_scale : -INFINITY;
        s2 = v2 ? s2 * inv_scale : -INFINITY;

        float m = fmaxf(fmaxf(s0, s1), s2);
        #pragma unroll
        for (int off = 16; off; off >>= 1)
            m = fmaxf(m, __shfl_xor_sync(0xffffffffu, m, off));

        const bool any = (m > -INFINITY);
        float e0 = (v0 && any) ? __expf(s0 - m) : 0.f;
        float e1 = (v1 && any) ? __expf(s1 - m) : 0.f;
        float e2 = (v2 && any) ? __expf(s2 - m) : 0.f;  // identical on all lanes

        float ssum = e0 + e1;
        #pragma unroll
        for (int off = 16; off; off >>= 1)
            ssum += __shfl_xor_sync(0xffffffffu, ssum, off);
        ssum += e2;
        const float inv = any ? (1.0f / ssum) : 0.f;

        Pr[w][l]      = e0 * inv;
        Pr[w][l + 32] = e1 * inv;
        if (l == 0) Pr[w][64] = e2 * inv;
        __syncwarp();

        float acc0 = 0.f, acc1 = 0.f;
        #pragma unroll 1
        for (int off = 0; off < 65; off++) {
            int jg = ig - PWH + off;
            jg = min(max(jg, 0), PS - 1);  // clamp: p==0 for invalid, addr safe
            const float* vr = v + base + (size_t)jg * PH;
            const float p = Pr[w][off];
            acc0 += p * vr[l];
            acc1 += p * vr[l + 32];
        }
        out[base + (size_t)ig * PH + l]      = acc0;
        out[base + (size_t)ig * PH + l + 32] = acc1;
        __syncwarp();
    }
}

// ---------------------------------------------------------------------------
extern "C" void kernel_launch(void* const* d_in, const int* in_sizes, int n_in,
                              void* d_out, int out_size)
{
    const float* x    = (const float*)d_in[0];
    const int*   mask = (const int*)  d_in[1];
    const float* Wq   = (const float*)d_in[2];
    const float* bq   = (const float*)d_in[3];
    const float* Wk   = (const float*)d_in[4];
    const float* bk   = (const float*)d_in[5];
    const float* Wv   = (const float*)d_in[6];
    const float* bv   = (const float*)d_in[7];
    const float* Wo   = (const float*)d_in[8];
    const float* bo   = (const float*)d_in[9];
    float* out = (float*)d_out;

    float *qp, *kp, *vp, *ap;
    cudaGetSymbolAddress((void**)&qp, g_q);
    cudaGetSymbolAddress((void**)&kp, g_k);
    cudaGetSymbolAddress((void**)&vp, g_v);
    cudaGetSymbolAddress((void**)&ap, g_a);

    dim3 ggrid(1024 / 128, PM / 128);  // (8, 64)
    gemm_bias_kernel<<<ggrid, 256>>>(x, Wq, bq, qp);
    gemm_bias_kernel<<<ggrid, 256>>>(x, Wk, bk, kp);
    gemm_bias_kernel<<<ggrid, 256>>>(x, Wv, bv, vp);

    attn_kernel<<<PB * PNH * (PS / 32), 256>>>(qp, kp, vp, mask, ap);

    gemm_bias_kernel<<<ggrid, 256>>>(ap, Wo, bo, out);
}

// round 5
// speedup vs baseline: 2.3702x; 2.3702x over previous
#include <cuda_runtime.h>
#include <cuda_bf16.h>
#include <math.h>
#include <stdint.h>

// Problem constants
#define PB   4
#define PS   2048
#define PH   1024      // hidden = NH*HD
#define PNH  16
#define PHD  64
#define PWH  32        // window half = WIN//2
#define PM   (PB*PS)   // 8192 GEMM rows

// Scratch (allocation-free): q, k, v, attn-out, each [B,S,NH*HD] fp32
#define SCR_ELEMS (PB*PS*PH)
__device__ float g_q[SCR_ELEMS];
__device__ float g_k[SCR_ELEMS];
__device__ float g_v[SCR_ELEMS];
__device__ float g_a[SCR_ELEMS];

// ---------------------------------------------------------------------------
// TF32 helpers
// ---------------------------------------------------------------------------
__device__ __forceinline__ float to_tf32(float x) {
    uint32_t u;
    asm("cvt.rna.tf32.f32 %0, %1;" : "=r"(u) : "f"(x));
    return __uint_as_float(u);
}

__device__ __forceinline__ void mma_tf32(float* c, const float* a, const float* b) {
    asm volatile(
        "mma.sync.aligned.m16n8k8.row.col.f32.tf32.tf32.f32 "
        "{%0,%1,%2,%3}, {%4,%5,%6,%7}, {%8,%9}, {%0,%1,%2,%3};"
        : "+f"(c[0]), "+f"(c[1]), "+f"(c[2]), "+f"(c[3])
        : "r"(__float_as_uint(a[0])), "r"(__float_as_uint(a[1])),
          "r"(__float_as_uint(a[2])), "r"(__float_as_uint(a[3])),
          "r"(__float_as_uint(b[0])), "r"(__float_as_uint(b[1])));
}

// ---------------------------------------------------------------------------
// GEMM (TF32 tensor core): C[M,1024] = A[M,1024] @ W[1024,1024] + bias
// 128x128 block, BK=32, 8 warps (2m x 4n), warp tile 64x32, m16n8k8 mma
// ---------------------------------------------------------------------------
#define GK 1024
#define GN 1024
#define SA 36    // As row stride: (4g+tg)%32 bijective -> conflict-free frags
#define SB 136   // Bs row stride: (8tg+g)%32 bijective -> conflict-free frags

__global__ __launch_bounds__(256) void gemm_tf32_kernel(
    const float* __restrict__ A, const float* __restrict__ W,
    const float* __restrict__ bias, float* __restrict__ C)
{
    __shared__ float As[128][SA];  // [m][k]
    __shared__ float Bs[32][SB];   // [k][n]

    const int tid = threadIdx.x;
    const int m0 = blockIdx.y * 128;
    const int n0 = blockIdx.x * 128;
    const int warp = tid >> 5;
    const int lane = tid & 31;
    const int g  = lane >> 2;   // groupID 0..7
    const int tg = lane & 3;    // thread-in-group 0..3
    const int wm = (warp & 1) * 64;   // warp m offset in block
    const int wn = (warp >> 1) * 32;  // warp n offset in block

    float acc[4][4][4];
    #pragma unroll
    for (int mi = 0; mi < 4; mi++)
        #pragma unroll
        for (int ni = 0; ni < 4; ni++)
            #pragma unroll
            for (int r = 0; r < 4; r++) acc[mi][ni][r] = 0.f;

    const float* Ab = A + (size_t)m0 * GK;

    for (int k0 = 0; k0 < GK; k0 += 32) {
        // A tile: 128 rows x 32 k (8 float4 per row), tf32-convert on the way in
        #pragma unroll
        for (int i = 0; i < 4; i++) {
            int idx = tid + i * 256;
            int r  = idx >> 3;
            int c4 = (idx & 7) << 2;
            float4 v = *(const float4*)(Ab + (size_t)r * GK + k0 + c4);
            v.x = to_tf32(v.x); v.y = to_tf32(v.y);
            v.z = to_tf32(v.z); v.w = to_tf32(v.w);
            *(float4*)(&As[r][c4]) = v;
        }
        // B tile: 32 k rows x 128 n cols
        #pragma unroll
        for (int i = 0; i < 4; i++) {
            int idx = tid + i * 256;
            int r  = idx >> 5;
            int c4 = (idx & 31) << 2;
            float4 v = *(const float4*)(W + (size_t)(k0 + r) * GN + n0 + c4);
            v.x = to_tf32(v.x); v.y = to_tf32(v.y);
            v.z = to_tf32(v.z); v.w = to_tf32(v.w);
            *(float4*)(&Bs[r][c4]) = v;
        }
        __syncthreads();

        #pragma unroll
        for (int ks = 0; ks < 4; ks++) {
            const int kb = ks * 8;
            float af[4][4], bf[4][2];
            #pragma unroll
            for (int mi = 0; mi < 4; mi++) {
                const int mr = wm + mi * 16 + g;
                af[mi][0] = As[mr    ][kb + tg];
                af[mi][1] = As[mr + 8][kb + tg];
                af[mi][2] = As[mr    ][kb + tg + 4];
                af[mi][3] = As[mr + 8][kb + tg + 4];
            }
            #pragma unroll
            for (int ni = 0; ni < 4; ni++) {
                const int nc = wn + ni * 8 + g;
                bf[ni][0] = Bs[kb + tg    ][nc];
                bf[ni][1] = Bs[kb + tg + 4][nc];
            }
            #pragma unroll
            for (int mi = 0; mi < 4; mi++)
                #pragma unroll
                for (int ni = 0; ni < 4; ni++)
                    mma_tf32(acc[mi][ni], af[mi], bf[ni]);
        }
        __syncthreads();
    }

    // Epilogue: bias + float2 stores
    #pragma unroll
    for (int mi = 0; mi < 4; mi++) {
        const int row0 = m0 + wm + mi * 16 + g;
        #pragma unroll
        for (int ni = 0; ni < 4; ni++) {
            const int col = n0 + wn + ni * 8 + tg * 2;
            const float2 bv = *(const float2*)(bias + col);
            float2 o0, o1;
            o0.x = acc[mi][ni][0] + bv.x; o0.y = acc[mi][ni][1] + bv.y;
            o1.x = acc[mi][ni][2] + bv.x; o1.y = acc[mi][ni][3] + bv.y;
            *(float2*)(C + (size_t)row0 * GN + col)       = o0;
            *(float2*)(C + (size_t)(row0 + 8) * GN + col) = o1;
        }
    }
}

// ---------------------------------------------------------------------------
// Banded attention: unchanged from R2 (366us; optimize next round)
// ---------------------------------------------------------------------------
__global__ __launch_bounds__(256) void attn_kernel(
    const float* __restrict__ q, const float* __restrict__ k,
    const float* __restrict__ v, const int* __restrict__ mask,
    float* __restrict__ out)
{
    constexpr int QT = 32;
    constexpr int KT = QT + 2 * PWH;  // 96
    __shared__ float Ks[KT][PHD + 1];
    __shared__ float Qs[QT][PHD];
    __shared__ float Pr[8][72];

    const int nqt = PS / QT;
    const int blk = blockIdx.x;
    const int qt = blk % nqt;
    const int h  = (blk / nqt) % PNH;
    const int b  = blk / (nqt * PNH);
    const int t0 = qt * QT;
    const int tid = threadIdx.x;
    const size_t base = ((size_t)b * PS) * PH + (size_t)h * PHD;

    for (int idx = tid; idx < KT * (PHD / 4); idx += 256) {
        int r  = idx >> 4;
        int c4 = (idx & 15) << 2;
        int jg = t0 - PWH + r;
        float4 kv = make_float4(0.f, 0.f, 0.f, 0.f);
        if (jg >= 0 && jg < PS)
            kv = *(const float4*)(k + base + (size_t)jg * PH + c4);
        Ks[r][c4 + 0] = kv.x; Ks[r][c4 + 1] = kv.y;
        Ks[r][c4 + 2] = kv.z; Ks[r][c4 + 3] = kv.w;
    }
    for (int idx = tid; idx < QT * (PHD / 4); idx += 256) {
        int r  = idx >> 4;
        int c4 = (idx & 15) << 2;
        *(float4*)(&Qs[r][c4]) =
            *(const float4*)(q + base + (size_t)(t0 + r) * PH + c4);
    }
    __syncthreads();

    const int w = tid >> 5, l = tid & 31;
    const float inv_scale = 0.125f;

    for (int qi = w; qi < QT; qi += 8) {
        const int ig = t0 + qi;
        const int j0 = ig - PWH + l;
        const int j1 = j0 + 32;
        const int j2 = ig + PWH;
        const bool v0 = (j0 >= 0) && (j0 < PS) && (mask[b * PS + j0] != 0);
        const bool v1 = (j1 < PS) && (mask[b * PS + j1] != 0);
        const bool v2 = (j2 < PS) && (mask[b * PS + j2] != 0);

        float s0 = 0.f, s1 = 0.f, s2 = 0.f;
        #pragma unroll 16
        for (int d = 0; d < PHD; d++) {
            float qd = Qs[qi][d];
            s0 += qd * Ks[qi + l][d];
            s1 += qd * Ks[qi + l + 32][d];
            s2 += qd * Ks[qi + 64][d];
        }
        s0 = v0 ? s0 * inv_scale : -INFINITY;
        s1 = v1 ? s1 * inv_scale : -INFINITY;
        s2 = v2 ? s2 * inv_scale : -INFINITY;

        float m = fmaxf(fmaxf(s0, s1), s2);
        #pragma unroll
        for (int off = 16; off; off >>= 1)
            m = fmaxf(m, __shfl_xor_sync(0xffffffffu, m, off));

        const bool any = (m > -INFINITY);
        float e0 = (v0 && any) ? __expf(s0 - m) : 0.f;
        float e1 = (v1 && any) ? __expf(s1 - m) : 0.f;
        float e2 = (v2 && any) ? __expf(s2 - m) : 0.f;

        float ssum = e0 + e1;
        #pragma unroll
        for (int off = 16; off; off >>= 1)
            ssum += __shfl_xor_sync(0xffffffffu, ssum, off);
        ssum += e2;
        const float inv = any ? (1.0f / ssum) : 0.f;

        Pr[w][l]      = e0 * inv;
        Pr[w][l + 32] = e1 * inv;
        if (l == 0) Pr[w][64] = e2 * inv;
        __syncwarp();

        float acc0 = 0.f, acc1 = 0.f;
        #pragma unroll 1
        for (int off = 0; off < 65; off++) {
            int jg = ig - PWH + off;
            jg = min(max(jg, 0), PS - 1);
            const float* vr = v + base + (size_t)jg * PH;
            const float p = Pr[w][off];
            acc0 += p * vr[l];
            acc1 += p * vr[l + 32];
        }
        out[base + (size_t)ig * PH + l]      = acc0;
        out[base + (size_t)ig * PH + l + 32] = acc1;
        __syncwarp();
    }
}

// ---------------------------------------------------------------------------
extern "C" void kernel_launch(void* const* d_in, const int* in_sizes, int n_in,
                              void* d_out, int out_size)
{
    const float* x    = (const float*)d_in[0];
    const int*   mask = (const int*)  d_in[1];
    const float* Wq   = (const float*)d_in[2];
    const float* bq   = (const float*)d_in[3];
    const float* Wk   = (const float*)d_in[4];
    const float* bk   = (const float*)d_in[5];
    const float* Wv   = (const float*)d_in[6];
    const float* bv   = (const float*)d_in[7];
    const float* Wo   = (const float*)d_in[8];
    const float* bo   = (const float*)d_in[9];
    float* out = (float*)d_out;

    float *qp, *kp, *vp, *ap;
    cudaGetSymbolAddress((void**)&qp, g_q);
    cudaGetSymbolAddress((void**)&kp, g_k);
    cudaGetSymbolAddress((void**)&vp, g_v);
    cudaGetSymbolAddress((void**)&ap, g_a);

    dim3 ggrid(GN / 128, PM / 128);  // (8, 64)
    gemm_tf32_kernel<<<ggrid, 256>>>(x, Wq, bq, qp);
    gemm_tf32_kernel<<<ggrid, 256>>>(x, Wk, bk, kp);
    gemm_tf32_kernel<<<ggrid, 256>>>(x, Wv, bv, vp);

    attn_kernel<<<PB * PNH * (PS / 32), 256>>>(qp, kp, vp, mask, ap);

    gemm_tf32_kernel<<<ggrid, 256>>>(ap, Wo, bo, out);
}

// round 6
// speedup vs baseline: 3.0114x; 1.2706x over previous
#include <cuda_runtime.h>
#include <cuda_bf16.h>
#include <math.h>
#include <stdint.h>

// Problem constants
#define PB   4
#define PS   2048
#define PH   1024      // hidden = NH*HD
#define PNH  16
#define PHD  64
#define PWH  32        // window half = WIN//2
#define PM   (PB*PS)   // 8192 GEMM rows

// Scratch (allocation-free): q, k, v, attn-out, each [B,S,NH*HD] fp32
#define SCR_ELEMS (PB*PS*PH)
__device__ float g_q[SCR_ELEMS];
__device__ float g_k[SCR_ELEMS];
__device__ float g_v[SCR_ELEMS];
__device__ float g_a[SCR_ELEMS];

// ---------------------------------------------------------------------------
// TF32 helpers
// ---------------------------------------------------------------------------
__device__ __forceinline__ float to_tf32(float x) {
    uint32_t u;
    asm("cvt.rna.tf32.f32 %0, %1;" : "=r"(u) : "f"(x));
    return __uint_as_float(u);
}

__device__ __forceinline__ void mma_tf32(float* c, const float* a, const float* b) {
    asm volatile(
        "mma.sync.aligned.m16n8k8.row.col.f32.tf32.tf32.f32 "
        "{%0,%1,%2,%3}, {%4,%5,%6,%7}, {%8,%9}, {%0,%1,%2,%3};"
        : "+f"(c[0]), "+f"(c[1]), "+f"(c[2]), "+f"(c[3])
        : "r"(__float_as_uint(a[0])), "r"(__float_as_uint(a[1])),
          "r"(__float_as_uint(a[2])), "r"(__float_as_uint(a[3])),
          "r"(__float_as_uint(b[0])), "r"(__float_as_uint(b[1])));
}

// ---------------------------------------------------------------------------
// GEMM (TF32 tensor core): unchanged from R5 (~137us each)
// ---------------------------------------------------------------------------
#define GK 1024
#define GN 1024
#define SA 36
#define SB 136

__global__ __launch_bounds__(256) void gemm_tf32_kernel(
    const float* __restrict__ A, const float* __restrict__ W,
    const float* __restrict__ bias, float* __restrict__ C)
{
    __shared__ float As[128][SA];  // [m][k]
    __shared__ float Bs[32][SB];   // [k][n]

    const int tid = threadIdx.x;
    const int m0 = blockIdx.y * 128;
    const int n0 = blockIdx.x * 128;
    const int warp = tid >> 5;
    const int lane = tid & 31;
    const int g  = lane >> 2;
    const int tg = lane & 3;
    const int wm = (warp & 1) * 64;
    const int wn = (warp >> 1) * 32;

    float acc[4][4][4];
    #pragma unroll
    for (int mi = 0; mi < 4; mi++)
        #pragma unroll
        for (int ni = 0; ni < 4; ni++)
            #pragma unroll
            for (int r = 0; r < 4; r++) acc[mi][ni][r] = 0.f;

    const float* Ab = A + (size_t)m0 * GK;

    for (int k0 = 0; k0 < GK; k0 += 32) {
        #pragma unroll
        for (int i = 0; i < 4; i++) {
            int idx = tid + i * 256;
            int r  = idx >> 3;
            int c4 = (idx & 7) << 2;
            float4 v = *(const float4*)(Ab + (size_t)r * GK + k0 + c4);
            v.x = to_tf32(v.x); v.y = to_tf32(v.y);
            v.z = to_tf32(v.z); v.w = to_tf32(v.w);
            *(float4*)(&As[r][c4]) = v;
        }
        #pragma unroll
        for (int i = 0; i < 4; i++) {
            int idx = tid + i * 256;
            int r  = idx >> 5;
            int c4 = (idx & 31) << 2;
            float4 v = *(const float4*)(W + (size_t)(k0 + r) * GN + n0 + c4);
            v.x = to_tf32(v.x); v.y = to_tf32(v.y);
            v.z = to_tf32(v.z); v.w = to_tf32(v.w);
            *(float4*)(&Bs[r][c4]) = v;
        }
        __syncthreads();

        #pragma unroll
        for (int ks = 0; ks < 4; ks++) {
            const int kb = ks * 8;
            float af[4][4], bf[4][2];
            #pragma unroll
            for (int mi = 0; mi < 4; mi++) {
                const int mr = wm + mi * 16 + g;
                af[mi][0] = As[mr    ][kb + tg];
                af[mi][1] = As[mr + 8][kb + tg];
                af[mi][2] = As[mr    ][kb + tg + 4];
                af[mi][3] = As[mr + 8][kb + tg + 4];
            }
            #pragma unroll
            for (int ni = 0; ni < 4; ni++) {
                const int nc = wn + ni * 8 + g;
                bf[ni][0] = Bs[kb + tg    ][nc];
                bf[ni][1] = Bs[kb + tg + 4][nc];
            }
            #pragma unroll
            for (int mi = 0; mi < 4; mi++)
                #pragma unroll
                for (int ni = 0; ni < 4; ni++)
                    mma_tf32(acc[mi][ni], af[mi], bf[ni]);
        }
        __syncthreads();
    }

    #pragma unroll
    for (int mi = 0; mi < 4; mi++) {
        const int row0 = m0 + wm + mi * 16 + g;
        #pragma unroll
        for (int ni = 0; ni < 4; ni++) {
            const int col = n0 + wn + ni * 8 + tg * 2;
            const float2 bv = *(const float2*)(bias + col);
            float2 o0, o1;
            o0.x = acc[mi][ni][0] + bv.x; o0.y = acc[mi][ni][1] + bv.y;
            o1.x = acc[mi][ni][2] + bv.x; o1.y = acc[mi][ni][3] + bv.y;
            *(float2*)(C + (size_t)row0 * GN + col)       = o0;
            *(float2*)(C + (size_t)(row0 + 8) * GN + col) = o1;
        }
    }
}

// ---------------------------------------------------------------------------
// Banded attention v2: warp owns 4 CONSECUTIVE queries.
// Score phase: float4 LDS from Ks (stride 68 -> conflict-free).
// V phase: band-row-indexed probabilities; each of the warp's 68 V band rows
// loaded ONCE (float2 per lane) and applied to all 4 query accumulators.
// ---------------------------------------------------------------------------
#define KSTR 68   // Ks row stride in floats (68%32==4 -> LDS.128 conflict-free)

__global__ __launch_bounds__(256) void attn_kernel(
    const float* __restrict__ q, const float* __restrict__ k,
    const float* __restrict__ v, const int* __restrict__ mask,
    float* __restrict__ out)
{
    constexpr int QT = 32;            // queries per block
    constexpr int KT = QT + 2 * PWH;  // 96 score band rows
    __shared__ float Ks[KT * KSTR];   // 26112 B
    __shared__ float Qs[QT][PHD];     // 8192 B
    __shared__ float Pr4[8][4][68];   // 8704 B: [warp][query][band row]

    const int nqt = PS / QT;          // 64
    const int blk = blockIdx.x;
    const int qt = blk % nqt;
    const int h  = (blk / nqt) % PNH;
    const int b  = blk / (nqt * PNH);
    const int t0 = qt * QT;
    const int tid = threadIdx.x;
    const size_t base = ((size_t)b * PS) * PH + (size_t)h * PHD;

    // Load K band tile (rows t0-32 .. t0+63), zero-fill out-of-range
    for (int idx = tid; idx < KT * (PHD / 4); idx += 256) {
        int r  = idx >> 4;
        int c4 = (idx & 15) << 2;
        int jg = t0 - PWH + r;
        float4 kv = make_float4(0.f, 0.f, 0.f, 0.f);
        if (jg >= 0 && jg < PS)
            kv = *(const float4*)(k + base + (size_t)jg * PH + c4);
        *(float4*)(&Ks[r * KSTR + c4]) = kv;
    }
    // Load Q tile
    for (int idx = tid; idx < QT * (PHD / 4); idx += 256) {
        int r  = idx >> 4;
        int c4 = (idx & 15) << 2;
        *(float4*)(&Qs[r][c4]) =
            *(const float4*)(q + base + (size_t)(t0 + r) * PH + c4);
    }
    __syncthreads();

    const int w = tid >> 5, l = tid & 31;
    const float inv_scale = 0.125f;  // 1/sqrt(64)

    // ---- Score + softmax for this warp's 4 consecutive queries ----
    #pragma unroll
    for (int qi = 0; qi < 4; qi++) {
        const int ql = 4 * w + qi;        // local query 0..31
        const int ig = t0 + ql;           // global query index
        const int j0 = ig - PWH + l;      // key for offset l
        const int j1 = j0 + 32;
        const int j2 = ig + PWH;          // offset 64 (broadcast)
        const bool v0 = (j0 >= 0) && (j0 < PS) && (mask[b * PS + j0] != 0);
        const bool v1 = (j1 < PS) && (mask[b * PS + j1] != 0);
        const bool v2 = (j2 < PS) && (mask[b * PS + j2] != 0);

        const float4* K0 = (const float4*)(&Ks[(ql + l)      * KSTR]);
        const float4* K1 = (const float4*)(&Ks[(ql + l + 32) * KSTR]);
        const float4* K2 = (const float4*)(&Ks[(ql + 64)     * KSTR]);
        const float4* Qv = (const float4*)(&Qs[ql][0]);

        float s0 = 0.f, s1 = 0.f, s2 = 0.f;
        #pragma unroll
        for (int d4 = 0; d4 < PHD / 4; d4++) {
            float4 qv = Qv[d4];
            float4 a = K0[d4], c = K1[d4], e = K2[d4];
            s0 += qv.x * a.x + qv.y * a.y + qv.z * a.z + qv.w * a.w;
            s1 += qv.x * c.x + qv.y * c.y + qv.z * c.z + qv.w * c.w;
            s2 += qv.x * e.x + qv.y * e.y + qv.z * e.z + qv.w * e.w;
        }
        s0 = v0 ? s0 * inv_scale : -INFINITY;
        s1 = v1 ? s1 * inv_scale : -INFINITY;
        s2 = v2 ? s2 * inv_scale : -INFINITY;

        float m = fmaxf(fmaxf(s0, s1), s2);
        #pragma unroll
        for (int off = 16; off; off >>= 1)
            m = fmaxf(m, __shfl_xor_sync(0xffffffffu, m, off));

        const bool any = (m > -INFINITY);
        float e0 = (v0 && any) ? __expf(s0 - m) : 0.f;
        float e1 = (v1 && any) ? __expf(s1 - m) : 0.f;
        float e2 = (v2 && any) ? __expf(s2 - m) : 0.f;  // same on all lanes

        float ssum = e0 + e1;
        #pragma unroll
        for (int off = 16; off; off >>= 1)
            ssum += __shfl_xor_sync(0xffffffffu, ssum, off);
        ssum += e2;
        const float inv = any ? (1.0f / ssum) : 0.f;

        // Zero full band row range, then write this query's window rows.
        // Band row r corresponds to global key (t0 + 4w - 32 + r); query qi's
        // window occupies rows [qi, qi+64].
        #pragma unroll
        for (int r = l; r < 68; r += 32) Pr4[w][qi][r] = 0.f;
        __syncwarp();
        Pr4[w][qi][qi + l]      = e0 * inv;
        Pr4[w][qi][qi + l + 32] = e1 * inv;
        if (l == 0) Pr4[w][qi][qi + 64] = e2 * inv;
        __syncwarp();
    }

    // ---- Shared V pass: 68 band rows, each loaded once, feeds 4 queries ----
    const int r0g = t0 + 4 * w - PWH;   // global key of band row 0
    float2 a0 = make_float2(0.f, 0.f), a1 = a0, a2 = a0, a3 = a0;

    #pragma unroll 4
    for (int r = 0; r < 68; r++) {
        int jg = r0g + r;
        jg = min(max(jg, 0), PS - 1);   // clamp addr; probs are 0 when invalid
        const float2 vv = *(const float2*)(v + base + (size_t)jg * PH + 2 * l);
        const float p0 = Pr4[w][0][r];
        const float p1 = Pr4[w][1][r];
        const float p2 = Pr4[w][2][r];
        const float p3 = Pr4[w][3][r];
        a0.x += p0 * vv.x; a0.y += p0 * vv.y;
        a1.x += p1 * vv.x; a1.y += p1 * vv.y;
        a2.x += p2 * vv.x; a2.y += p2 * vv.y;
        a3.x += p3 * vv.x; a3.y += p3 * vv.y;
    }

    {
        const int ig0 = t0 + 4 * w;
        float* o = (float*)(out + base + (size_t)ig0 * PH + 2 * l);
        *(float2*)(o)             = a0;
        *(float2*)(o + PH)        = a1;
        *(float2*)(o + 2 * PH)    = a2;
        *(float2*)(o + 3 * PH)    = a3;
    }
}

// ---------------------------------------------------------------------------
extern "C" void kernel_launch(void* const* d_in, const int* in_sizes, int n_in,
                              void* d_out, int out_size)
{
    const float* x    = (const float*)d_in[0];
    const int*   mask = (const int*)  d_in[1];
    const float* Wq   = (const float*)d_in[2];
    const float* bq   = (const float*)d_in[3];
    const float* Wk   = (const float*)d_in[4];
    const float* bk   = (const float*)d_in[5];
    const float* Wv   = (const float*)d_in[6];
    const float* bv   = (const float*)d_in[7];
    const float* Wo   = (const float*)d_in[8];
    const float* bo   = (const float*)d_in[9];
    float* out = (float*)d_out;

    float *qp, *kp, *vp, *ap;
    cudaGetSymbolAddress((void**)&qp, g_q);
    cudaGetSymbolAddress((void**)&kp, g_k);
    cudaGetSymbolAddress((void**)&vp, g_v);
    cudaGetSymbolAddress((void**)&ap, g_a);

    dim3 ggrid(GN / 128, PM / 128);  // (8, 64)
    gemm_tf32_kernel<<<ggrid, 256>>>(x, Wq, bq, qp);
    gemm_tf32_kernel<<<ggrid, 256>>>(x, Wk, bk, kp);
    gemm_tf32_kernel<<<ggrid, 256>>>(x, Wv, bv, vp);

    attn_kernel<<<PB * PNH * (PS / 32), 256>>>(qp, kp, vp, mask, ap);

    gemm_tf32_kernel<<<ggrid, 256>>>(ap, Wo, bo, out);
}